// round 1
// baseline (speedup 1.0000x reference)
#include <cuda_runtime.h>
#include <cuda_bf16.h>

#define B_  8
#define N_  1024
#define C_  768
#define H_  12
#define HD_ 64
#define BH_ (B_*H_)          // 96
#define M_  (B_*N_)          // 8192
constexpr float SCALE = 0.125f;  // 64^-0.5

// ---- scratch (device globals: no allocation allowed) ----
__device__ float g_q[B_*H_*N_*HD_];    // [b][h][n][d]
__device__ float g_k[B_*H_*N_*HD_];
__device__ float g_v[B_*H_*N_*HD_];
__device__ float g_ctx[B_*N_*C_];      // [b][n][c]

// ============================================================
// Kernel 1: QKV GEMM  y = x @ w_qkv, scattered into g_q/g_k/g_v
// Classic 128x128x8 SGEMM, 256 threads, 8x8 per thread.
// ============================================================
__global__ __launch_bounds__(256) void qkv_gemm(const float* __restrict__ x,
                                                const float* __restrict__ w) {
    __shared__ float As[8][128];
    __shared__ float Bs[8][128];
    const int tid = threadIdx.x;
    const int bx = blockIdx.x, by = blockIdx.y;
    const int ty = tid >> 4, tx = tid & 15;

    float acc[8][8];
#pragma unroll
    for (int i = 0; i < 8; i++)
#pragma unroll
        for (int j = 0; j < 8; j++) acc[i][j] = 0.f;

    const int arow = by * 128 + (tid >> 1);
    const int acol = (tid & 1) * 4;
    const int brow = tid >> 5;
    const int bcol = bx * 128 + (tid & 31) * 4;
    const float* Ap = x + arow * 768 + acol;
    const float* Bp = w + brow * 2304 + bcol;

    for (int kt = 0; kt < 768; kt += 8) {
        float4 a = *(const float4*)(Ap + kt);
        As[acol + 0][tid >> 1] = a.x;
        As[acol + 1][tid >> 1] = a.y;
        As[acol + 2][tid >> 1] = a.z;
        As[acol + 3][tid >> 1] = a.w;
        *(float4*)&Bs[brow][(tid & 31) * 4] = *(const float4*)(Bp + (long)kt * 2304);
        __syncthreads();
#pragma unroll
        for (int k = 0; k < 8; k++) {
            float ra[8], rb[8];
            *(float4*)&ra[0] = *(const float4*)&As[k][ty * 8];
            *(float4*)&ra[4] = *(const float4*)&As[k][ty * 8 + 4];
            *(float4*)&rb[0] = *(const float4*)&Bs[k][tx * 8];
            *(float4*)&rb[4] = *(const float4*)&Bs[k][tx * 8 + 4];
#pragma unroll
            for (int i = 0; i < 8; i++)
#pragma unroll
                for (int j = 0; j < 8; j++)
                    acc[i][j] += ra[i] * rb[j];
        }
        __syncthreads();
    }

    // scatter epilogue into per-head layouts
    const int m0 = by * 128 + ty * 8;
    const int n0 = bx * 128 + tx * 8;
#pragma unroll
    for (int i = 0; i < 8; i++) {
        const int m = m0 + i;
        const int b = m >> 10, tok = m & 1023;
#pragma unroll
        for (int j = 0; j < 8; j++) {
            const int n = n0 + j;
            const int sec = n / 768;
            const int r = n - sec * 768;
            const int h = r >> 6, d = r & 63;
            float* dst = (sec == 0) ? g_q : ((sec == 1) ? g_k : g_v);
            dst[((b * H_ + h) * N_ + tok) * HD_ + d] = acc[i][j];
        }
    }
}

// ============================================================
// Kernel 2: flash attention, fp32, 64-row Q tile per CTA.
//   Qt: [d][r] (scaled), KP: K as [d][c] then P as [r][k], Vs: [k][d]
//   256 threads: ty=tid/16 owns 4 rows, tx=tid%16 owns 4 cols.
// ============================================================
__global__ __launch_bounds__(256) void attn_kernel() {
    __shared__ float Qt[64 * 64];
    __shared__ float KP[64 * 64];
    __shared__ float Vs[64 * 64];
    const int tid = threadIdx.x;
    const int ty = tid >> 4, tx = tid & 15;
    const int q0 = blockIdx.x * 64;
    const int bh = blockIdx.y;
    const float* qbase = g_q + (long)bh * N_ * HD_;
    const float* kbase = g_k + (long)bh * N_ * HD_;
    const float* vbase = g_v + (long)bh * N_ * HD_;

    // load Q tile transposed + pre-scaled
    {
        const int row = tid >> 2;
        const int d0 = (tid & 3) * 16;
        const float* src = qbase + (q0 + row) * 64 + d0;
#pragma unroll
        for (int u = 0; u < 4; u++) {
            float4 v4 = *(const float4*)(src + u * 4);
            Qt[(d0 + u * 4 + 0) * 64 + row] = v4.x * SCALE;
            Qt[(d0 + u * 4 + 1) * 64 + row] = v4.y * SCALE;
            Qt[(d0 + u * 4 + 2) * 64 + row] = v4.z * SCALE;
            Qt[(d0 + u * 4 + 3) * 64 + row] = v4.w * SCALE;
        }
    }

    float o[4][4];
    float mi[4], li[4];
#pragma unroll
    for (int i = 0; i < 4; i++) {
        mi[i] = -1e30f; li[i] = 0.f;
#pragma unroll
        for (int j = 0; j < 4; j++) o[i][j] = 0.f;
    }

    for (int kt0 = 0; kt0 < N_; kt0 += 64) {
        // load K (transposed) and V (natural)
        {
            const int row = tid >> 2;
            const int d0 = (tid & 3) * 16;
            const float* ks = kbase + (kt0 + row) * 64 + d0;
            const float* vs = vbase + (kt0 + row) * 64 + d0;
#pragma unroll
            for (int u = 0; u < 4; u++) {
                float4 k4 = *(const float4*)(ks + u * 4);
                KP[(d0 + u * 4 + 0) * 64 + row] = k4.x;
                KP[(d0 + u * 4 + 1) * 64 + row] = k4.y;
                KP[(d0 + u * 4 + 2) * 64 + row] = k4.z;
                KP[(d0 + u * 4 + 3) * 64 + row] = k4.w;
                *(float4*)&Vs[row * 64 + d0 + u * 4] = *(const float4*)(vs + u * 4);
            }
        }
        __syncthreads();

        // S = Q K^T (4x4 per thread)
        float s[4][4];
#pragma unroll
        for (int i = 0; i < 4; i++)
#pragma unroll
            for (int j = 0; j < 4; j++) s[i][j] = 0.f;
#pragma unroll 16
        for (int d = 0; d < 64; d++) {
            float4 qa = *(const float4*)&Qt[d * 64 + ty * 4];
            float4 kb = *(const float4*)&KP[d * 64 + tx * 4];
            s[0][0] += qa.x * kb.x; s[0][1] += qa.x * kb.y; s[0][2] += qa.x * kb.z; s[0][3] += qa.x * kb.w;
            s[1][0] += qa.y * kb.x; s[1][1] += qa.y * kb.y; s[1][2] += qa.y * kb.z; s[1][3] += qa.y * kb.w;
            s[2][0] += qa.z * kb.x; s[2][1] += qa.z * kb.y; s[2][2] += qa.z * kb.z; s[2][3] += qa.z * kb.w;
            s[3][0] += qa.w * kb.x; s[3][1] += qa.w * kb.y; s[3][2] += qa.w * kb.z; s[3][3] += qa.w * kb.w;
        }
        __syncthreads();   // all KP (K) reads done before P overwrite

        // online softmax update; 16-lane xor all-reduce (lanes of one ty share a half-warp)
#pragma unroll
        for (int i = 0; i < 4; i++) {
            float rmax = fmaxf(fmaxf(s[i][0], s[i][1]), fmaxf(s[i][2], s[i][3]));
#pragma unroll
            for (int off = 8; off >= 1; off >>= 1)
                rmax = fmaxf(rmax, __shfl_xor_sync(0xffffffffu, rmax, off));
            const float mn = fmaxf(mi[i], rmax);
            const float fac = __expf(mi[i] - mn);
            float rs = 0.f;
#pragma unroll
            for (int j = 0; j < 4; j++) { s[i][j] = __expf(s[i][j] - mn); rs += s[i][j]; }
#pragma unroll
            for (int off = 8; off >= 1; off >>= 1)
                rs += __shfl_xor_sync(0xffffffffu, rs, off);
            li[i] = li[i] * fac + rs;
            mi[i] = mn;
#pragma unroll
            for (int j = 0; j < 4; j++) o[i][j] *= fac;
        }

        // store P naturally [r][k] into KP
#pragma unroll
        for (int i = 0; i < 4; i++)
            *(float4*)&KP[(ty * 4 + i) * 64 + tx * 4] =
                make_float4(s[i][0], s[i][1], s[i][2], s[i][3]);
        __syncthreads();

        // O += P V
#pragma unroll
        for (int k4 = 0; k4 < 16; k4++) {
            float pr[4][4];
#pragma unroll
            for (int i = 0; i < 4; i++)
                *(float4*)pr[i] = *(const float4*)&KP[(ty * 4 + i) * 64 + k4 * 4];
#pragma unroll
            for (int u = 0; u < 4; u++) {
                float4 vv = *(const float4*)&Vs[(k4 * 4 + u) * 64 + tx * 4];
#pragma unroll
                for (int i = 0; i < 4; i++) {
                    o[i][0] += pr[i][u] * vv.x;
                    o[i][1] += pr[i][u] * vv.y;
                    o[i][2] += pr[i][u] * vv.z;
                    o[i][3] += pr[i][u] * vv.w;
                }
            }
        }
        __syncthreads();   // KP/Vs reads done before next tile load
    }

    // normalize + write context [b][tok][h*64+d]
    const int b = bh / H_, h = bh - b * H_;
#pragma unroll
    for (int i = 0; i < 4; i++) {
        const float inv = 1.f / li[i];
        const int tok = q0 + ty * 4 + i;
        float4 r = make_float4(o[i][0] * inv, o[i][1] * inv, o[i][2] * inv, o[i][3] * inv);
        *(float4*)&g_ctx[((long)(b * N_ + tok)) * C_ + h * HD_ + tx * 4] = r;
    }
}

// ============================================================
// Kernel 3: out projection  out = ctx @ w_out + b_out
// ============================================================
__global__ __launch_bounds__(256) void out_gemm(const float* __restrict__ w,
                                                const float* __restrict__ bias,
                                                float* __restrict__ out) {
    __shared__ float As[8][128];
    __shared__ float Bs[8][128];
    const int tid = threadIdx.x;
    const int bx = blockIdx.x, by = blockIdx.y;
    const int ty = tid >> 4, tx = tid & 15;

    float acc[8][8];
#pragma unroll
    for (int i = 0; i < 8; i++)
#pragma unroll
        for (int j = 0; j < 8; j++) acc[i][j] = 0.f;

    const int arow = by * 128 + (tid >> 1);
    const int acol = (tid & 1) * 4;
    const int brow = tid >> 5;
    const int bcol = bx * 128 + (tid & 31) * 4;
    const float* Ap = g_ctx + (long)arow * 768 + acol;
    const float* Bp = w + brow * 768 + bcol;

    for (int kt = 0; kt < 768; kt += 8) {
        float4 a = *(const float4*)(Ap + kt);
        As[acol + 0][tid >> 1] = a.x;
        As[acol + 1][tid >> 1] = a.y;
        As[acol + 2][tid >> 1] = a.z;
        As[acol + 3][tid >> 1] = a.w;
        *(float4*)&Bs[brow][(tid & 31) * 4] = *(const float4*)(Bp + (long)kt * 768);
        __syncthreads();
#pragma unroll
        for (int k = 0; k < 8; k++) {
            float ra[8], rb[8];
            *(float4*)&ra[0] = *(const float4*)&As[k][ty * 8];
            *(float4*)&ra[4] = *(const float4*)&As[k][ty * 8 + 4];
            *(float4*)&rb[0] = *(const float4*)&Bs[k][tx * 8];
            *(float4*)&rb[4] = *(const float4*)&Bs[k][tx * 8 + 4];
#pragma unroll
            for (int i = 0; i < 8; i++)
#pragma unroll
                for (int j = 0; j < 8; j++)
                    acc[i][j] += ra[i] * rb[j];
        }
        __syncthreads();
    }

    const int m0 = by * 128 + ty * 8;
    const int n0 = bx * 128 + tx * 8;
#pragma unroll
    for (int i = 0; i < 8; i++) {
        const int m = m0 + i;
#pragma unroll
        for (int j4 = 0; j4 < 8; j4 += 4) {
            const int n = n0 + j4;
            float4 bb = *(const float4*)(bias + n);
            float4 r = make_float4(acc[i][j4 + 0] + bb.x, acc[i][j4 + 1] + bb.y,
                                   acc[i][j4 + 2] + bb.z, acc[i][j4 + 3] + bb.w);
            *(float4*)&out[(long)m * 768 + n] = r;
        }
    }
}

// ============================================================
extern "C" void kernel_launch(void* const* d_in, const int* in_sizes, int n_in,
                              void* d_out, int out_size) {
    const float* x     = (const float*)d_in[0];
    const float* w_qkv = (const float*)d_in[1];
    const float* w_out = (const float*)d_in[2];
    const float* b_out = (const float*)d_in[3];
    float* out = (float*)d_out;

    qkv_gemm<<<dim3(2304 / 128, M_ / 128), 256>>>(x, w_qkv);
    attn_kernel<<<dim3(N_ / 64, BH_), 256>>>();
    out_gemm<<<dim3(768 / 128, M_ / 128), 256>>>(w_out, b_out, out);
}

// round 4
// speedup vs baseline: 2.4146x; 2.4146x over previous
#include <cuda_runtime.h>
#include <cuda_bf16.h>
#include <cstdint>

#define B_  8
#define N_  1024
#define C_  768
#define H_  12
#define HD_ 64
#define BH_ (B_*H_)          // 96
#define M_  (B_*N_)          // 8192
constexpr float SCALE = 0.125f;  // 64^-0.5

// ---- scratch ----
__device__ float g_q[B_*H_*N_*HD_];    // [b][h][n][d]
__device__ float g_k[B_*H_*N_*HD_];    // [b][h][n][d]
__device__ float g_v[B_*H_*HD_*N_];    // [b][h][d][n]  (transposed!)
__device__ float g_ctx[B_*N_*C_];      // [b][n][c]

// ---- helpers ----
__device__ __forceinline__ uint32_t f2tf(float f) {
    uint32_t u; asm("cvt.rna.tf32.f32 %0, %1;" : "=r"(u) : "f"(f)); return u;
}
__device__ __forceinline__ void ldsm4(uint32_t& r0, uint32_t& r1, uint32_t& r2, uint32_t& r3,
                                      const uint32_t* p) {
    uint32_t a = (uint32_t)__cvta_generic_to_shared(p);
    asm volatile("ldmatrix.sync.aligned.m8n8.x4.shared.b16 {%0,%1,%2,%3}, [%4];"
                 : "=r"(r0), "=r"(r1), "=r"(r2), "=r"(r3) : "r"(a));
}
__device__ __forceinline__ void mma8(float* c, const uint32_t* a, const uint32_t* b) {
    asm volatile("mma.sync.aligned.m16n8k8.row.col.f32.tf32.tf32.f32 "
                 "{%0,%1,%2,%3},{%4,%5,%6,%7},{%8,%9},{%0,%1,%2,%3};"
                 : "+f"(c[0]), "+f"(c[1]), "+f"(c[2]), "+f"(c[3])
                 : "r"(a[0]), "r"(a[1]), "r"(a[2]), "r"(a[3]), "r"(b[0]), "r"(b[1]));
}

// swizzled word index: K=32-wide rows (A tiles in GEMM)
#define AIDX(m,k) ((m)*32 + (((((k)>>2) ^ ((m)&7)))<<2) + ((k)&3))
// swizzled word index: 64-wide rows (attention tiles)
#define SIDX(r,c) ((r)*64 + (((((c)>>2) ^ ((r)&7)))<<2) + ((c)&3))
#define BPAD 136

// ============================================================
// Kernel 1: QKV GEMM (tf32 MMA) y = x @ w_qkv -> g_q/g_k/g_v
// ============================================================
__global__ __launch_bounds__(256, 2) void qkv_gemm(const float* __restrict__ x,
                                                   const float* __restrict__ w) {
    __shared__ uint32_t As[128 * 32];
    __shared__ uint32_t Bs[32 * BPAD];
    const int tid = threadIdx.x, lane = tid & 31, warp = tid >> 5;
    const int wm = warp >> 1, wn = warp & 1;

    float acc[2][8][4];
#pragma unroll
    for (int i = 0; i < 2; i++)
#pragma unroll
        for (int j = 0; j < 8; j++)
#pragma unroll
            for (int r = 0; r < 4; r++) acc[i][j][r] = 0.f;

    const int am = tid >> 1, ak = (tid & 1) * 16;
    const float* ap = x + (size_t)(blockIdx.y * 128 + am) * 768 + ak;
    const int bk = (tid >> 5) * 4, bn = (tid & 31) * 4;
    const float* bp = w + (size_t)bk * 2304 + blockIdx.x * 128 + bn;

    for (int kt = 0; kt < 768; kt += 32) {
#pragma unroll
        for (int u = 0; u < 4; u++) {
            float4 v = *(const float4*)(ap + kt + u * 4);
            uint4 t = make_uint4(f2tf(v.x), f2tf(v.y), f2tf(v.z), f2tf(v.w));
            *(uint4*)&As[AIDX(am, ak + u * 4)] = t;
        }
#pragma unroll
        for (int u = 0; u < 4; u++) {
            float4 v = *(const float4*)(bp + (size_t)(kt + u) * 2304);
            uint4 t = make_uint4(f2tf(v.x), f2tf(v.y), f2tf(v.z), f2tf(v.w));
            *(uint4*)&Bs[(bk + u) * BPAD + bn] = t;
        }
        __syncthreads();
#pragma unroll
        for (int ks = 0; ks < 4; ks++) {
            uint32_t a[2][4], b[8][2];
#pragma unroll
            for (int i = 0; i < 2; i++) {
                const int row = wm * 32 + i * 16 + ((lane >> 3) & 1) * 8 + (lane & 7);
                const int grp = ks * 2 + (lane >> 4);
                ldsm4(a[i][0], a[i][1], a[i][2], a[i][3],
                      &As[row * 32 + ((grp ^ (row & 7)) << 2)]);
            }
#pragma unroll
            for (int j = 0; j < 8; j++) {
                const int n = wn * 64 + j * 8 + (lane >> 2);
                b[j][0] = Bs[(ks * 8 + (lane & 3)) * BPAD + n];
                b[j][1] = Bs[(ks * 8 + 4 + (lane & 3)) * BPAD + n];
            }
#pragma unroll
            for (int i = 0; i < 2; i++)
#pragma unroll
                for (int j = 0; j < 8; j++) mma8(acc[i][j], a[i], b[j]);
        }
        __syncthreads();
    }

    // epilogue: warp covers exactly one head section (64 cols)
    const int n0 = blockIdx.x * 128 + wn * 64;
    const int sec = n0 / 768;
    const int h = (n0 - sec * 768) >> 6;
#pragma unroll
    for (int i = 0; i < 2; i++)
#pragma unroll
        for (int li = 0; li < 2; li++) {
            const int m = blockIdx.y * 128 + wm * 32 + i * 16 + li * 8 + (lane >> 2);
            const int b = m >> 10, tok = m & 1023;
            if (sec < 2) {
                float* base = (sec == 0 ? g_q : g_k) +
                              ((size_t)(b * H_ + h) * 1024 + tok) * 64 + 2 * (lane & 3);
#pragma unroll
                for (int j = 0; j < 8; j++)
                    *(float2*)(base + j * 8) = make_float2(acc[i][j][li * 2], acc[i][j][li * 2 + 1]);
            } else {
                float* base = g_v + (size_t)(b * H_ + h) * 65536 + tok;
#pragma unroll
                for (int j = 0; j < 8; j++) {
                    const int d = j * 8 + 2 * (lane & 3);
                    base[(size_t)d * 1024]       = acc[i][j][li * 2];
                    base[(size_t)(d + 1) * 1024] = acc[i][j][li * 2 + 1];
                }
            }
        }
}

// ============================================================
// Kernel 2: flash attention (tf32 MMA), 64 q-rows per CTA, 4 warps
// ============================================================
__global__ __launch_bounds__(128) void attn_kernel() {
    __shared__ uint32_t Qs[64 * 64];
    __shared__ uint32_t Ks[64 * 64];   // K tile, then reused for P
    __shared__ uint32_t Vs[64 * 64];   // V^T tile [d][tok]
    const int tid = threadIdx.x, lane = tid & 31, warp = tid >> 5;
    const int q0 = blockIdx.x * 64, bh = blockIdx.y;

    // load Q (scaled, tf32)
    {
        const int row = tid >> 1, half = tid & 1;
        const float* qp = g_q + ((size_t)bh * 1024 + q0 + row) * 64 + half * 32;
#pragma unroll
        for (int u = 0; u < 8; u++) {
            float4 v = *(const float4*)(qp + u * 4);
            uint4 t = make_uint4(f2tf(v.x * SCALE), f2tf(v.y * SCALE),
                                 f2tf(v.z * SCALE), f2tf(v.w * SCALE));
            *(uint4*)&Qs[SIDX(row, half * 32 + u * 4)] = t;
        }
    }

    float o[8][4];
#pragma unroll
    for (int j = 0; j < 8; j++)
#pragma unroll
        for (int r = 0; r < 4; r++) o[j][r] = 0.f;
    float mA = -1e30f, mB = -1e30f, lA = 0.f, lB = 0.f;

    const float* kbase = g_k + (size_t)bh * 65536;
    const float* vbase = g_v + (size_t)bh * 65536;

    for (int kt = 0; kt < 1024; kt += 64) {
        {   // load K tile [tok][d] and V^T tile [d][tok]
            const int row = tid >> 1, half = tid & 1;
            const float* kp = kbase + (size_t)(kt + row) * 64 + half * 32;
            const float* vp = vbase + (size_t)row * 1024 + kt + half * 32;
#pragma unroll
            for (int u = 0; u < 8; u++) {
                float4 kv = *(const float4*)(kp + u * 4);
                *(uint4*)&Ks[SIDX(row, half * 32 + u * 4)] =
                    make_uint4(f2tf(kv.x), f2tf(kv.y), f2tf(kv.z), f2tf(kv.w));
                float4 vv = *(const float4*)(vp + u * 4);
                *(uint4*)&Vs[SIDX(row, half * 32 + u * 4)] =
                    make_uint4(f2tf(vv.x), f2tf(vv.y), f2tf(vv.z), f2tf(vv.w));
            }
        }
        __syncthreads();

        // S = Q K^T   (warp: rows warp*16..+15, all 64 cols)
        float s[8][4];
#pragma unroll
        for (int j = 0; j < 8; j++)
#pragma unroll
            for (int r = 0; r < 4; r++) s[j][r] = 0.f;
#pragma unroll
        for (int ks = 0; ks < 8; ks++) {
            uint32_t a[4], b[8][2];
            {
                const int row = warp * 16 + ((lane >> 3) & 1) * 8 + (lane & 7);
                const int grp = ks * 2 + (lane >> 4);
                ldsm4(a[0], a[1], a[2], a[3], &Qs[row * 64 + ((grp ^ (row & 7)) << 2)]);
            }
#pragma unroll
            for (int jp = 0; jp < 4; jp++) {
                const int row = jp * 16 + ((lane >> 4) & 1) * 8 + (lane & 7);
                const int grp = ks * 2 + ((lane >> 3) & 1);
                ldsm4(b[2 * jp][0], b[2 * jp][1], b[2 * jp + 1][0], b[2 * jp + 1][1],
                      &Ks[row * 64 + ((grp ^ (row & 7)) << 2)]);
            }
#pragma unroll
            for (int j = 0; j < 8; j++) mma8(s[j], a, b[j]);
        }
        __syncthreads();   // everyone done reading K before P overwrite

        // online softmax: rows ra = warp*16+(lane>>2), rb = ra+8
        float mxa = -1e30f, mxb = -1e30f;
#pragma unroll
        for (int j = 0; j < 8; j++) {
            mxa = fmaxf(mxa, fmaxf(s[j][0], s[j][1]));
            mxb = fmaxf(mxb, fmaxf(s[j][2], s[j][3]));
        }
#pragma unroll
        for (int off = 1; off <= 2; off <<= 1) {
            mxa = fmaxf(mxa, __shfl_xor_sync(0xffffffffu, mxa, off));
            mxb = fmaxf(mxb, __shfl_xor_sync(0xffffffffu, mxb, off));
        }
        const float mnA = fmaxf(mA, mxa), mnB = fmaxf(mB, mxb);
        const float facA = __expf(mA - mnA), facB = __expf(mB - mnB);
        mA = mnA; mB = mnB;
        float sa = 0.f, sb = 0.f;
#pragma unroll
        for (int j = 0; j < 8; j++) {
            s[j][0] = __expf(s[j][0] - mA); s[j][1] = __expf(s[j][1] - mA);
            s[j][2] = __expf(s[j][2] - mB); s[j][3] = __expf(s[j][3] - mB);
            sa += s[j][0] + s[j][1]; sb += s[j][2] + s[j][3];
        }
#pragma unroll
        for (int off = 1; off <= 2; off <<= 1) {
            sa += __shfl_xor_sync(0xffffffffu, sa, off);
            sb += __shfl_xor_sync(0xffffffffu, sb, off);
        }
        lA = lA * facA + sa; lB = lB * facB + sb;
#pragma unroll
        for (int j = 0; j < 8; j++) {
            o[j][0] *= facA; o[j][1] *= facA; o[j][2] *= facB; o[j][3] *= facB;
        }

        // store P (tf32) into Ks (own rows only)
        {
            const int ra = warp * 16 + (lane >> 2), rb = ra + 8;
#pragma unroll
            for (int j = 0; j < 8; j++) {
                const int c0 = j * 8 + 2 * (lane & 3);
                *(uint2*)&Ks[SIDX(ra, c0)] = make_uint2(f2tf(s[j][0]), f2tf(s[j][1]));
                *(uint2*)&Ks[SIDX(rb, c0)] = make_uint2(f2tf(s[j][2]), f2tf(s[j][3]));
            }
        }
        __syncwarp();

        // O += P V   (A = P from Ks own rows, B = V^T from Vs)
#pragma unroll
        for (int ks = 0; ks < 8; ks++) {
            uint32_t a[4], b[8][2];
            {
                const int row = warp * 16 + ((lane >> 3) & 1) * 8 + (lane & 7);
                const int grp = ks * 2 + (lane >> 4);
                ldsm4(a[0], a[1], a[2], a[3], &Ks[row * 64 + ((grp ^ (row & 7)) << 2)]);
            }
#pragma unroll
            for (int jp = 0; jp < 4; jp++) {
                const int row = jp * 16 + ((lane >> 4) & 1) * 8 + (lane & 7);
                const int grp = ks * 2 + ((lane >> 3) & 1);
                ldsm4(b[2 * jp][0], b[2 * jp][1], b[2 * jp + 1][0], b[2 * jp + 1][1],
                      &Vs[row * 64 + ((grp ^ (row & 7)) << 2)]);
            }
#pragma unroll
            for (int j = 0; j < 8; j++) mma8(o[j], a, b[j]);
        }
        __syncthreads();   // done reading Ks(P)/Vs before next tile load
    }

    // normalize + write ctx
    const int b = bh / H_, h = bh - b * H_;
    const int ra = warp * 16 + (lane >> 2);
    const float invA = 1.f / lA, invB = 1.f / lB;
    float* pa = g_ctx + ((size_t)(b * 1024) + q0 + ra) * 768 + h * 64 + 2 * (lane & 3);
    float* pb = g_ctx + ((size_t)(b * 1024) + q0 + ra + 8) * 768 + h * 64 + 2 * (lane & 3);
#pragma unroll
    for (int j = 0; j < 8; j++) {
        *(float2*)(pa + j * 8) = make_float2(o[j][0] * invA, o[j][1] * invA);
        *(float2*)(pb + j * 8) = make_float2(o[j][2] * invB, o[j][3] * invB);
    }
}

// ============================================================
// Kernel 3: out projection (tf32 MMA) out = ctx @ w_out + b_out
// ============================================================
__global__ __launch_bounds__(256, 2) void out_gemm(const float* __restrict__ w,
                                                   const float* __restrict__ bias,
                                                   float* __restrict__ out) {
    __shared__ uint32_t As[128 * 32];
    __shared__ uint32_t Bs[32 * BPAD];
    const int tid = threadIdx.x, lane = tid & 31, warp = tid >> 5;
    const int wm = warp >> 1, wn = warp & 1;

    float acc[2][8][4];
#pragma unroll
    for (int i = 0; i < 2; i++)
#pragma unroll
        for (int j = 0; j < 8; j++)
#pragma unroll
            for (int r = 0; r < 4; r++) acc[i][j][r] = 0.f;

    const int am = tid >> 1, ak = (tid & 1) * 16;
    const float* ap = g_ctx + (size_t)(blockIdx.y * 128 + am) * 768 + ak;
    const int bk = (tid >> 5) * 4, bn = (tid & 31) * 4;
    const float* bp = w + (size_t)bk * 768 + blockIdx.x * 128 + bn;

    for (int kt = 0; kt < 768; kt += 32) {
#pragma unroll
        for (int u = 0; u < 4; u++) {
            float4 v = *(const float4*)(ap + kt + u * 4);
            uint4 t = make_uint4(f2tf(v.x), f2tf(v.y), f2tf(v.z), f2tf(v.w));
            *(uint4*)&As[AIDX(am, ak + u * 4)] = t;
        }
#pragma unroll
        for (int u = 0; u < 4; u++) {
            float4 v = *(const float4*)(bp + (size_t)(kt + u) * 768);
            uint4 t = make_uint4(f2tf(v.x), f2tf(v.y), f2tf(v.z), f2tf(v.w));
            *(uint4*)&Bs[(bk + u) * BPAD + bn] = t;
        }
        __syncthreads();
#pragma unroll
        for (int ks = 0; ks < 4; ks++) {
            uint32_t a[2][4], b[8][2];
#pragma unroll
            for (int i = 0; i < 2; i++) {
                const int row = wm * 32 + i * 16 + ((lane >> 3) & 1) * 8 + (lane & 7);
                const int grp = ks * 2 + (lane >> 4);
                ldsm4(a[i][0], a[i][1], a[i][2], a[i][3],
                      &As[row * 32 + ((grp ^ (row & 7)) << 2)]);
            }
#pragma unroll
            for (int j = 0; j < 8; j++) {
                const int n = wn * 64 + j * 8 + (lane >> 2);
                b[j][0] = Bs[(ks * 8 + (lane & 3)) * BPAD + n];
                b[j][1] = Bs[(ks * 8 + 4 + (lane & 3)) * BPAD + n];
            }
#pragma unroll
            for (int i = 0; i < 2; i++)
#pragma unroll
                for (int j = 0; j < 8; j++) mma8(acc[i][j], a[i], b[j]);
        }
        __syncthreads();
    }

    const int n0 = blockIdx.x * 128 + wn * 64 + 2 * (lane & 3);
#pragma unroll
    for (int i = 0; i < 2; i++)
#pragma unroll
        for (int li = 0; li < 2; li++) {
            const int m = blockIdx.y * 128 + wm * 32 + i * 16 + li * 8 + (lane >> 2);
            float* op = out + (size_t)m * 768 + n0;
#pragma unroll
            for (int j = 0; j < 8; j++) {
                float2 bb = *(const float2*)(bias + n0 + j * 8);
                *(float2*)(op + j * 8) =
                    make_float2(acc[i][j][li * 2] + bb.x, acc[i][j][li * 2 + 1] + bb.y);
            }
        }
}

// ============================================================
extern "C" void kernel_launch(void* const* d_in, const int* in_sizes, int n_in,
                              void* d_out, int out_size) {
    const float* x     = (const float*)d_in[0];
    const float* w_qkv = (const float*)d_in[1];
    const float* w_out = (const float*)d_in[2];
    const float* b_out = (const float*)d_in[3];
    float* out = (float*)d_out;

    qkv_gemm<<<dim3(2304 / 128, M_ / 128), 256>>>(x, w_qkv);
    attn_kernel<<<dim3(N_ / 64, BH_), 128>>>();
    out_gemm<<<dim3(768 / 128, M_ / 128), 256>>>(w_out, b_out, out);
}